// round 1
// baseline (speedup 1.0000x reference)
#include <cuda_runtime.h>
#include <cuda_bf16.h>
#include <cstdint>

// Problem constants (fixed shapes per reference)
#define N_ROWS 16384
#define K_ROWS 2048
#define D_DIM  1024

#define BM 128
#define BN 128
#define BK 32
#define PAD 40                 // padded smem row length (bf16 elems) -> conflict-free frag LDS
#define NKT (D_DIM / BK)       // 32 k-tiles

// Scratch for precomputed squared norms (device globals: allocation-free)
__device__ float g_feat_sq[N_ROWS];
__device__ float g_cent_sq[K_ROWS];

// ---------------------------------------------------------------------------
// Row squared-norm kernel: one warp per row, fp32 accumulate.
// which==0 -> g_feat_sq, which==1 -> g_cent_sq
// ---------------------------------------------------------------------------
__global__ void row_norms_kernel(const float* __restrict__ src, int nrows, int which) {
    int row = blockIdx.x * blockDim.y + threadIdx.y;
    if (row >= nrows) return;
    const float4* p = reinterpret_cast<const float4*>(src) + (size_t)row * (D_DIM / 4);
    float s = 0.f;
#pragma unroll
    for (int i = threadIdx.x; i < D_DIM / 4; i += 32) {
        float4 v = p[i];
        s += v.x * v.x + v.y * v.y + v.z * v.z + v.w * v.w;
    }
#pragma unroll
    for (int o = 16; o > 0; o >>= 1) s += __shfl_xor_sync(0xffffffffu, s, o);
    if (threadIdx.x == 0) {
        if (which) g_cent_sq[row] = s;
        else       g_feat_sq[row] = s;
    }
}

// ---------------------------------------------------------------------------
// mma.sync m16n8k16 bf16 wrapper (row.col, f32 accum)
// ---------------------------------------------------------------------------
__device__ __forceinline__ void mma16816(float* c, const uint32_t* a, const uint32_t* b) {
    asm volatile(
        "mma.sync.aligned.m16n8k16.row.col.f32.bf16.bf16.f32 "
        "{%0,%1,%2,%3}, {%4,%5,%6,%7}, {%8,%9}, {%0,%1,%2,%3};\n"
        : "+f"(c[0]), "+f"(c[1]), "+f"(c[2]), "+f"(c[3])
        : "r"(a[0]), "r"(a[1]), "r"(a[2]), "r"(a[3]), "r"(b[0]), "r"(b[1]));
}

// ---------------------------------------------------------------------------
// Fused distance GEMM:
//   cross = feat[BM rows] . centers[BN rows]^T  (bf16 tensor cores, fp32 accum)
//   out   = feat_sq[m] + cent_sq[n] - 2*cross
// Block: 256 threads = 8 warps, warp grid 2(M) x 4(N), warp tile 64x32.
// Double-buffered smem, fp32->bf16 convert on global->shared path.
// ---------------------------------------------------------------------------
__global__ __launch_bounds__(256, 1)
void dist_gemm_kernel(const float* __restrict__ feat,
                      const float* __restrict__ cent,
                      float* __restrict__ out) {
    __shared__ __align__(16) __nv_bfloat16 As[2][BM][PAD];
    __shared__ __align__(16) __nv_bfloat16 Bs[2][BN][PAD];

    const int tid  = threadIdx.x;
    const int warp = tid >> 5;
    const int lane = tid & 31;
    const int g    = lane >> 2;   // mma group (0..7)
    const int t    = lane & 3;    // thread-in-group (0..3)

    const int wm = (warp >> 2) * 64;  // warp M offset (0 or 64)
    const int wn = (warp & 3) * 32;   // warp N offset (0,32,64,96)

    const int m0 = blockIdx.y * BM;
    const int n0 = blockIdx.x * BN;

    float acc[4][4][4] = {};          // [im][in][creg]
    float4 ra[4], rb[4];              // gmem prefetch registers

    // --- tile loaders: 1024 float4 slots per tile, 4 per thread ---
    auto ldg_tiles = [&](int kt) {
#pragma unroll
        for (int j = 0; j < 4; j++) {
            int slot = j * 256 + tid;
            int row  = slot >> 3;          // 8 float4 per 32-wide k row
            int kq   = slot & 7;
            ra[j] = *reinterpret_cast<const float4*>(
                feat + (size_t)(m0 + row) * D_DIM + kt * BK + kq * 4);
            rb[j] = *reinterpret_cast<const float4*>(
                cent + (size_t)(n0 + row) * D_DIM + kt * BK + kq * 4);
        }
    };
    auto sts_tiles = [&](int buf) {
#pragma unroll
        for (int j = 0; j < 4; j++) {
            int slot = j * 256 + tid;
            int row  = slot >> 3;
            int kq   = slot & 7;
            __nv_bfloat162* pa = reinterpret_cast<__nv_bfloat162*>(&As[buf][row][kq * 4]);
            pa[0] = __floats2bfloat162_rn(ra[j].x, ra[j].y);
            pa[1] = __floats2bfloat162_rn(ra[j].z, ra[j].w);
            __nv_bfloat162* pb = reinterpret_cast<__nv_bfloat162*>(&Bs[buf][row][kq * 4]);
            pb[0] = __floats2bfloat162_rn(rb[j].x, rb[j].y);
            pb[1] = __floats2bfloat162_rn(rb[j].z, rb[j].w);
        }
    };

    ldg_tiles(0);
    sts_tiles(0);
    __syncthreads();

    for (int kt = 0; kt < NKT; kt++) {
        if (kt + 1 < NKT) ldg_tiles(kt + 1);
        const int buf = kt & 1;

#pragma unroll
        for (int kk = 0; kk < BK; kk += 16) {
            uint32_t a[4][4], b[4][2];
#pragma unroll
            for (int im = 0; im < 4; im++) {
                int r = wm + im * 16 + g;
                a[im][0] = *reinterpret_cast<const uint32_t*>(&As[buf][r    ][kk + 2 * t    ]);
                a[im][1] = *reinterpret_cast<const uint32_t*>(&As[buf][r + 8][kk + 2 * t    ]);
                a[im][2] = *reinterpret_cast<const uint32_t*>(&As[buf][r    ][kk + 2 * t + 8]);
                a[im][3] = *reinterpret_cast<const uint32_t*>(&As[buf][r + 8][kk + 2 * t + 8]);
            }
#pragma unroll
            for (int in = 0; in < 4; in++) {
                int c = wn + in * 8 + g;
                b[in][0] = *reinterpret_cast<const uint32_t*>(&Bs[buf][c][kk + 2 * t    ]);
                b[in][1] = *reinterpret_cast<const uint32_t*>(&Bs[buf][c][kk + 2 * t + 8]);
            }
#pragma unroll
            for (int im = 0; im < 4; im++)
#pragma unroll
                for (int in = 0; in < 4; in++)
                    mma16816(acc[im][in], a[im], b[in]);
        }

        if (kt + 1 < NKT) sts_tiles((kt + 1) & 1);
        __syncthreads();
    }

    // --- epilogue: out = feat_sq[m] + cent_sq[n] - 2*cross ---
#pragma unroll
    for (int im = 0; im < 4; im++) {
        int gm = m0 + wm + im * 16 + g;
        float fs0 = g_feat_sq[gm];
        float fs1 = g_feat_sq[gm + 8];
#pragma unroll
        for (int in = 0; in < 4; in++) {
            int gn = n0 + wn + in * 8 + 2 * t;
            float cs0 = g_cent_sq[gn];
            float cs1 = g_cent_sq[gn + 1];
            float2 v0, v1;
            v0.x = fs0 + cs0 - 2.f * acc[im][in][0];
            v0.y = fs0 + cs1 - 2.f * acc[im][in][1];
            v1.x = fs1 + cs0 - 2.f * acc[im][in][2];
            v1.y = fs1 + cs1 - 2.f * acc[im][in][3];
            *reinterpret_cast<float2*>(out + (size_t)gm * K_ROWS + gn)       = v0;
            *reinterpret_cast<float2*>(out + (size_t)(gm + 8) * K_ROWS + gn) = v1;
        }
    }
}

// ---------------------------------------------------------------------------
extern "C" void kernel_launch(void* const* d_in, const int* in_sizes, int n_in,
                              void* d_out, int out_size) {
    const float* feat = (const float*)d_in[0];
    const float* cent = (const float*)d_in[1];
    float* out = (float*)d_out;

    dim3 nb(32, 8);
    row_norms_kernel<<<N_ROWS / 8, nb>>>(feat, N_ROWS, 0);
    row_norms_kernel<<<K_ROWS / 8, nb>>>(cent, K_ROWS, 1);

    dim3 grid(K_ROWS / BN, N_ROWS / BM);
    dist_gemm_kernel<<<grid, 256>>>(feat, cent, out);
}

// round 3
// speedup vs baseline: 1.6933x; 1.6933x over previous
#include <cuda_runtime.h>
#include <cuda_bf16.h>
#include <cstdint>

// ---------------------------------------------------------------------------
// Problem constants
// ---------------------------------------------------------------------------
#define N_ROWS 16384
#define K_ROWS 2048
#define D_DIM  1024

#define BM 128
#define BN 128
#define BK 64                   // bf16 -> 128 B per smem row (SW128 atom)
#define NKT (D_DIM / BK)        // 16 k-tiles
#define STAGES 3
#define A_STAGE_BYTES (BM * 128)          // 16 KB
#define B_STAGE_BYTES (BN * 128)          // 16 KB
#define STAGE_BYTES (A_STAGE_BYTES + B_STAGE_BYTES)   // 32 KB
#define SM_ALLOC (STAGES * STAGE_BYTES)               // 96 KB

// bf16 mirrors + squared norms (device globals: allocation-free scratch)
__device__ __nv_bfloat16 g_feat_bf[(size_t)N_ROWS * D_DIM];   // 32 MB
__device__ __nv_bfloat16 g_cent_bf[(size_t)K_ROWS * D_DIM];   //  4 MB
__device__ float g_feat_sq[N_ROWS];
__device__ float g_cent_sq[K_ROWS];

// ---------------------------------------------------------------------------
// helpers
// ---------------------------------------------------------------------------
__device__ __forceinline__ void cp_async16(uint32_t saddr, const void* gaddr) {
    asm volatile("cp.async.cg.shared.global [%0], [%1], 16;" :: "r"(saddr), "l"(gaddr));
}

__device__ __forceinline__ void ldsm_x4(uint32_t* r, uint32_t addr) {
    asm volatile("ldmatrix.sync.aligned.m8n8.x4.shared.b16 {%0,%1,%2,%3}, [%4];"
                 : "=r"(r[0]), "=r"(r[1]), "=r"(r[2]), "=r"(r[3]) : "r"(addr));
}

__device__ __forceinline__ void mma16816(float* c, const uint32_t* a,
                                         uint32_t b0, uint32_t b1) {
    asm volatile(
        "mma.sync.aligned.m16n8k16.row.col.f32.bf16.bf16.f32 "
        "{%0,%1,%2,%3}, {%4,%5,%6,%7}, {%8,%9}, {%0,%1,%2,%3};\n"
        : "+f"(c[0]), "+f"(c[1]), "+f"(c[2]), "+f"(c[3])
        : "r"(a[0]), "r"(a[1]), "r"(a[2]), "r"(a[3]), "r"(b0), "r"(b1));
}

// ---------------------------------------------------------------------------
// fp32 -> bf16 conversion fused with row squared-norms. One warp per row.
// Covers both tensors in one launch (rows >= N_ROWS map to centers).
// ---------------------------------------------------------------------------
__global__ void convert_norms_kernel(const float* __restrict__ feat,
                                     const float* __restrict__ cent) {
    int grow = blockIdx.x * 8 + (threadIdx.x >> 5);
    int lane = threadIdx.x & 31;
    const float* src;
    __nv_bfloat16* dst;
    float* sq;
    int row;
    if (grow < N_ROWS) { src = feat; dst = g_feat_bf; sq = g_feat_sq; row = grow; }
    else               { src = cent; dst = g_cent_bf; sq = g_cent_sq; row = grow - N_ROWS; }

    const float4* p = reinterpret_cast<const float4*>(src) + (size_t)row * (D_DIM / 4);
    uint2* d = reinterpret_cast<uint2*>(dst + (size_t)row * D_DIM);
    float s = 0.f;
#pragma unroll
    for (int i = lane; i < D_DIM / 4; i += 32) {
        float4 v = p[i];
        s += v.x * v.x + v.y * v.y + v.z * v.z + v.w * v.w;
        __nv_bfloat162 lo = __floats2bfloat162_rn(v.x, v.y);
        __nv_bfloat162 hi = __floats2bfloat162_rn(v.z, v.w);
        uint2 u;
        u.x = *reinterpret_cast<uint32_t*>(&lo);
        u.y = *reinterpret_cast<uint32_t*>(&hi);
        d[i] = u;
    }
#pragma unroll
    for (int o = 16; o > 0; o >>= 1) s += __shfl_xor_sync(0xffffffffu, s, o);
    if (lane == 0) sq[row] = s;
}

// ---------------------------------------------------------------------------
// Distance GEMM: cross = feat_bf[128] . cent_bf[128]^T via mma.sync bf16,
// 3-stage cp.async pipeline, SW128 swizzle, ldmatrix fragment loads.
// out = feat_sq[m] + cent_sq[n] - 2*cross
// 256 threads = 8 warps (2 M x 4 N), warp tile 64 x 32.
// ---------------------------------------------------------------------------
__global__ void __launch_bounds__(256, 2)
dist_gemm_kernel(float* __restrict__ out) {
    extern __shared__ __align__(1024) char smem[];
    const uint32_t smem_u = (uint32_t)__cvta_generic_to_shared(smem);

    const int tid  = threadIdx.x;
    const int warp = tid >> 5;
    const int lane = tid & 31;

    const int wm = (warp >> 2) * 64;   // warp M offset: 0 / 64
    const int wn = (warp & 3) * 32;    // warp N offset: 0 / 32 / 64 / 96

    const int m0 = blockIdx.y * BM;
    const int n0 = blockIdx.x * BN;

    // cp.async slot mapping: 1024 16B chunks per tile, 4 per thread
    const int ld_row = tid >> 1;            // 0..127 (2 threads per row)
    const int ld_q0  = (tid & 1) * 4;       // chunk 0..3 or 4..7

    const __nv_bfloat16* agbase = g_feat_bf + (size_t)(m0 + ld_row) * D_DIM + ld_q0 * 8;
    const __nv_bfloat16* bgbase = g_cent_bf + (size_t)(n0 + ld_row) * D_DIM + ld_q0 * 8;
    const uint32_t ld_sw_row = ld_row * 128;
    const uint32_t ld_rx     = (ld_row & 7) << 4;

    auto load_stage = [&](int s, int kt) {
        const uint32_t abase = smem_u + s * STAGE_BYTES;
        const uint32_t bbase = abase + A_STAGE_BYTES;
        const __nv_bfloat16* ag = agbase + kt * BK;
        const __nv_bfloat16* bg = bgbase + kt * BK;
#pragma unroll
        for (int j = 0; j < 4; j++) {
            uint32_t so = ld_sw_row + ((((ld_q0 + j) * 16) ^ ld_rx));
            cp_async16(abase + so, ag + j * 8);
            cp_async16(bbase + so, bg + j * 8);
        }
    };

    // ldmatrix lane addressing (constant parts)
    const int fr_lo = lane & 15;            // row within 16-row fragment
    const uint32_t fr_hi16 = (lane >> 4) * 16;  // k-byte offset 0/16

    uint32_t a_rowb[4], a_rx[4], b_rowb[2], b_rx[2];
#pragma unroll
    for (int im = 0; im < 4; im++) {
        int r = wm + im * 16 + fr_lo;
        a_rowb[im] = r * 128;
        a_rx[im]   = (r & 7) << 4;
    }
#pragma unroll
    for (int ib = 0; ib < 2; ib++) {
        int r = wn + ib * 16 + fr_lo;
        b_rowb[ib] = r * 128;
        b_rx[ib]   = (r & 7) << 4;
    }

    float acc[4][4][4] = {};   // [im][in][creg]

    // --- prologue: fill STAGES-1 stages ---
#pragma unroll
    for (int s = 0; s < STAGES - 1; s++) {
        load_stage(s, s);
        asm volatile("cp.async.commit_group;" ::: "memory");
    }

    for (int kt = 0; kt < NKT; kt++) {
        asm volatile("cp.async.wait_group %0;" :: "n"(STAGES - 2) : "memory");
        __syncthreads();

        if (kt + STAGES - 1 < NKT)
            load_stage((kt + STAGES - 1) % STAGES, kt + STAGES - 1);
        asm volatile("cp.async.commit_group;" ::: "memory");

        const uint32_t abase = smem_u + (kt % STAGES) * STAGE_BYTES;
        const uint32_t bbase = abase + A_STAGE_BYTES;

#pragma unroll
        for (int ks = 0; ks < 4; ks++) {
            const uint32_t kb = ks * 32 + fr_hi16;
            uint32_t a[4][4], bq[2][4];
#pragma unroll
            for (int im = 0; im < 4; im++)
                ldsm_x4(a[im], abase + a_rowb[im] + (kb ^ a_rx[im]));
#pragma unroll
            for (int ib = 0; ib < 2; ib++)
                ldsm_x4(bq[ib], bbase + b_rowb[ib] + (kb ^ b_rx[ib]));
#pragma unroll
            for (int im = 0; im < 4; im++) {
#pragma unroll
                for (int ib = 0; ib < 2; ib++) {
                    mma16816(acc[im][2 * ib],     a[im], bq[ib][0], bq[ib][2]);
                    mma16816(acc[im][2 * ib + 1], a[im], bq[ib][1], bq[ib][3]);
                }
            }
        }
    }

    // --- epilogue: out = fs[m] + cs[n] - 2 * cross ---
    const int g = lane >> 2;
    const int t = lane & 3;
#pragma unroll
    for (int im = 0; im < 4; im++) {
        int gm = m0 + wm + im * 16 + g;
        float fs0 = g_feat_sq[gm];
        float fs1 = g_feat_sq[gm + 8];
#pragma unroll
        for (int in = 0; in < 4; in++) {
            int gn = n0 + wn + in * 8 + 2 * t;
            float cs0 = g_cent_sq[gn];
            float cs1 = g_cent_sq[gn + 1];
            float2 v0, v1;
            v0.x = fs0 + cs0 - 2.f * acc[im][in][0];
            v0.y = fs0 + cs1 - 2.f * acc[im][in][1];
            v1.x = fs1 + cs0 - 2.f * acc[im][in][2];
            v1.y = fs1 + cs1 - 2.f * acc[im][in][3];
            *reinterpret_cast<float2*>(out + (size_t)gm * K_ROWS + gn)       = v0;
            *reinterpret_cast<float2*>(out + (size_t)(gm + 8) * K_ROWS + gn) = v1;
        }
    }
}

// ---------------------------------------------------------------------------
extern "C" void kernel_launch(void* const* d_in, const int* in_sizes, int n_in,
                              void* d_out, int out_size) {
    const float* feat = (const float*)d_in[0];
    const float* cent = (const float*)d_in[1];
    float* out = (float*)d_out;

    cudaFuncSetAttribute(dist_gemm_kernel,
                         cudaFuncAttributeMaxDynamicSharedMemorySize, SM_ALLOC);

    convert_norms_kernel<<<(N_ROWS + K_ROWS) / 8, 256>>>(feat, cent);

    dim3 grid(K_ROWS / BN, N_ROWS / BM);
    dist_gemm_kernel<<<grid, 256, SM_ALLOC>>>(out);
}